// round 5
// baseline (speedup 1.0000x reference)
#include <cuda_runtime.h>
#include <math.h>
#include <stdint.h>

// ---------------- problem constants ----------------
#define BGPT 4
#define TGPT 1024
#define DGPT 1024
#define HGPT 16
#define HDH  64
#define LGPT 8
#define VGPT 4096
#define MGPT (BGPT*TGPT)   // 4096 tokens
#define FGPT (4*DGPT)      // 4096 ff dim

// weight element offsets (int8 limb arrays)
#define SZ_WQ   ((size_t)LGPT*DGPT*DGPT)
#define SZ_W1   ((size_t)LGPT*FGPT*DGPT)
#define SZ_HEAD ((size_t)VGPT*DGPT)
#define O_WQ    ((size_t)0)
#define O_WK    (O_WQ + SZ_WQ)
#define O_WV    (O_WK + SZ_WQ)
#define O_WP    (O_WV + SZ_WQ)
#define O_W1    (O_WP + SZ_WQ)
#define O_W2    (O_W1 + SZ_W1)
#define O_WLG   (O_W2 + SZ_W1)
#define O_WDV   (O_WLG + SZ_HEAD)
#define WTOT    (O_WDV + SZ_HEAD)

// weight row-scale offsets (rows)
#define RO_WQ   0
#define RO_WK   8192
#define RO_WV   16384
#define RO_WP   24576
#define RO_W1   32768
#define RO_W2   65536
#define RO_WLG  73728
#define RO_WDV  77824
#define RO_TOT  81920

// ---------------- scratch (device globals) ----------------
__device__ float g_x [MGPT*DGPT];       // residual stream
__device__ float g_q [MGPT*DGPT];
__device__ float g_k [MGPT*DGPT];
__device__ float g_v [MGPT*DGPT];
__device__ float g_h [MGPT*DGPT];       // attn out
__device__ float g_ff[MGPT*FGPT];       // gelu out
__device__ int8_t g_wa[WTOT];           // weight limb 1
__device__ int8_t g_wb[WTOT];           // weight limb 2
__device__ int8_t g_qa[(size_t)MGPT*FGPT];  // activation limb 1
__device__ int8_t g_qb[(size_t)MGPT*FGPT];  // activation limb 2
__device__ float  g_sw[RO_TOT];         // weight row scales
__device__ float  g_sa[MGPT];           // activation row scales

// ---------------- PTX helpers ----------------
__device__ __forceinline__ uint32_t smem_u32(const void* p) {
    uint32_t a;
    asm("{ .reg .u64 t; cvta.to.shared.u64 t, %1; cvt.u32.u64 %0, t; }" : "=r"(a) : "l"(p));
    return a;
}
#define CP16(dst, src) \
    asm volatile("cp.async.cg.shared.global [%0], [%1], 16;\n" :: "r"(dst), "l"(src))
#define CPCOMMIT() asm volatile("cp.async.commit_group;\n" ::: "memory")
#define CPWAIT(n)  asm volatile("cp.async.wait_group %0;\n" :: "n"(n) : "memory")

__device__ __forceinline__ void ldm4s(uint32_t r[4], uint32_t addr)
{
    asm volatile("ldmatrix.sync.aligned.m8n8.x4.shared.b16 {%0,%1,%2,%3}, [%4];\n"
                 : "=r"(r[0]), "=r"(r[1]), "=r"(r[2]), "=r"(r[3]) : "r"(addr));
}
__device__ __forceinline__ void imma(int c[4], const uint32_t a[4], const uint32_t b[2])
{
    asm volatile(
        "mma.sync.aligned.m16n8k32.row.col.s32.s8.s8.s32 "
        "{%0,%1,%2,%3}, {%4,%5,%6,%7}, {%8,%9}, {%0,%1,%2,%3};\n"
        : "+r"(c[0]), "+r"(c[1]), "+r"(c[2]), "+r"(c[3])
        : "r"(a[0]), "r"(a[1]), "r"(a[2]), "r"(a[3]), "r"(b[0]), "r"(b[1]));
}
__device__ __forceinline__ uint32_t swz(uint32_t off) { return off ^ ((off >> 3) & 0x70); }

// ---------------- block reductions ----------------
__device__ __forceinline__ float blk_red(float v, float* red, int tid, int ismax)
{
    #pragma unroll
    for (int o = 16; o; o >>= 1) {
        float t = __shfl_xor_sync(0xffffffffu, v, o);
        v = ismax ? fmaxf(v, t) : (v + t);
    }
    if ((tid & 31) == 0) red[tid >> 5] = v;
    __syncthreads();
    if (tid < 32) {
        float t = (tid < 8) ? red[tid] : (ismax ? -1e30f : 0.f);
        #pragma unroll
        for (int o = 4; o; o >>= 1) {
            float u = __shfl_xor_sync(0xffffffffu, t, o);
            t = ismax ? fmaxf(t, u) : (t + u);
        }
        if (tid == 0) red[0] = t;
    }
    __syncthreads();
    float r = red[0];
    __syncthreads();
    return r;
}

// ---------------- quantize helpers ----------------
__device__ __forceinline__ void quant2(float v, float rq, int& a1, int& a2)
{
    float q = v * rq;
    q = fminf(fmaxf(q, -126.f), 126.f);
    float f1 = rintf(q);
    float f2 = rintf((q - f1) * 254.f);
    a1 = (int)f1;
    a2 = (int)f2;
}

// ---------------- embedding ----------------
__global__ void embed_kernel(const int* __restrict__ idx,
                             const float* __restrict__ tok,
                             const float* __restrict__ pos,
                             float* __restrict__ x)
{
    int i = blockIdx.x * blockDim.x + threadIdx.x;
    if (i >= MGPT * DGPT) return;
    int row = i / DGPT;
    int d   = i - row * DGPT;
    int t   = row & (TGPT - 1);
    x[i] = tok[(size_t)idx[row] * DGPT + d] + pos[(size_t)t * DGPT + d];
}

// ---------------- generic per-row quantize (fp32 [R,K] -> 2x int8 + scale) ----
__global__ void __launch_bounds__(256) quant_kernel(const float* __restrict__ in,
                                                    int8_t* __restrict__ q1,
                                                    int8_t* __restrict__ q2,
                                                    float* __restrict__ sc,
                                                    int K)
{
    int row = blockIdx.x;
    int tid = threadIdx.x;
    __shared__ float red[8];
    const float4* x4 = (const float4*)(in + (size_t)row * K);
    int n4 = K >> 2;

    float m = 0.f;
    for (int i = tid; i < n4; i += 256) {
        float4 v = x4[i];
        m = fmaxf(m, fmaxf(fmaxf(fabsf(v.x), fabsf(v.y)), fmaxf(fabsf(v.z), fabsf(v.w))));
    }
    m = blk_red(m, red, tid, 1);
    float sa = fmaxf(m, 1e-20f) * (1.f / 126.f);
    if (tid == 0) sc[row] = sa;
    float rq = 1.f / sa;

    char4* o1 = (char4*)(q1 + (size_t)row * K);
    char4* o2 = (char4*)(q2 + (size_t)row * K);
    for (int i = tid; i < n4; i += 256) {
        float4 v = x4[i];
        int a1, a2, b1, b2, c1, c2, d1, d2;
        quant2(v.x, rq, a1, a2); quant2(v.y, rq, b1, b2);
        quant2(v.z, rq, c1, c2); quant2(v.w, rq, d1, d2);
        o1[i] = make_char4((char)a1, (char)b1, (char)c1, (char)d1);
        o2[i] = make_char4((char)a2, (char)b2, (char)c2, (char)d2);
    }
}

// ---------------- fused layernorm + quantize (K = 1024) ----------------
__global__ void __launch_bounds__(256) lnq_kernel(const float* __restrict__ in,
                                                  int8_t* __restrict__ q1,
                                                  int8_t* __restrict__ q2,
                                                  float* __restrict__ sc,
                                                  const float* __restrict__ w,
                                                  const float* __restrict__ b)
{
    int row = blockIdx.x;
    int tid = threadIdx.x;
    __shared__ float red[8];
    const float4* x4 = (const float4*)(in + (size_t)row * DGPT);
    float4 v = x4[tid];

    float s = v.x + v.y + v.z + v.w;
    s = blk_red(s, red, tid, 0);
    float mean = s * (1.f / DGPT);

    float dx = v.x - mean, dy = v.y - mean, dz = v.z - mean, dw = v.w - mean;
    float qs = dx*dx + dy*dy + dz*dz + dw*dw;
    qs = blk_red(qs, red, tid, 0);
    float rstd = rsqrtf(qs * (1.f / DGPT) + 1e-5f);

    float4 wv = ((const float4*)w)[tid];
    float4 bv = ((const float4*)b)[tid];
    float nx = dx * rstd * wv.x + bv.x;
    float ny = dy * rstd * wv.y + bv.y;
    float nz = dz * rstd * wv.z + bv.z;
    float nw = dw * rstd * wv.w + bv.w;

    float m = fmaxf(fmaxf(fabsf(nx), fabsf(ny)), fmaxf(fabsf(nz), fabsf(nw)));
    m = blk_red(m, red, tid, 1);
    float sa = fmaxf(m, 1e-20f) * (1.f / 126.f);
    if (tid == 0) sc[row] = sa;
    float rq = 1.f / sa;

    int a1, a2, b1, b2, c1, c2, d1, d2;
    quant2(nx, rq, a1, a2); quant2(ny, rq, b1, b2);
    quant2(nz, rq, c1, c2); quant2(nw, rq, d1, d2);
    ((char4*)(q1 + (size_t)row * DGPT))[tid] = make_char4((char)a1, (char)b1, (char)c1, (char)d1);
    ((char4*)(q2 + (size_t)row * DGPT))[tid] = make_char4((char)a2, (char)b2, (char)c2, (char)d2);
}

// ---------------- int8 Ozaki GEMM: C[M,N] = (A·sa) @ (W·sb)^T --------------
// CTA tile 128(M) x 64(N), BK = 128 int8. 8 warps, warp tile 64x16.
// MODE: 0=+bias | 1=+bias,GELU | 2=+bias,+res | 3=plain
#define QS_A1 0
#define QS_A2 16384
#define QS_B1 32768
#define QS_B2 40960
#define QS_STG 49152
#define Q_SMEM (2*QS_STG)   // 98304 B

template<int MODE>
__global__ void __launch_bounds__(256) gemm8(
    const int8_t* __restrict__ A1g, const int8_t* __restrict__ A2g,
    const float* __restrict__ sA,
    const int8_t* __restrict__ B1g, const int8_t* __restrict__ B2g,
    const float* __restrict__ sB,
    const float* __restrict__ bias, const float* __restrict__ res,
    float* __restrict__ C, int M, int N, int K)
{
    extern __shared__ __align__(1024) char smc[];
    const uint32_t sb = smem_u32(smc);

    const int tid  = threadIdx.x;
    const int lane = tid & 31;
    const int wid  = tid >> 5;
    const int wm   = wid >> 2;          // 0..1
    const int wn   = wid & 3;           // 0..3
    const int bm   = blockIdx.y * 128;
    const int bn   = blockIdx.x * 64;

    int P0[4][2][4], P1[4][2][4], P2[4][2][4];
    #pragma unroll
    for (int mt = 0; mt < 4; mt++)
        #pragma unroll
        for (int nt = 0; nt < 2; nt++)
            #pragma unroll
            for (int r = 0; r < 4; r++) { P0[mt][nt][r] = 0; P1[mt][nt][r] = 0; P2[mt][nt][r] = 0; }

    const int8_t* pA1 = A1g + (size_t)bm * K;
    const int8_t* pA2 = A2g + (size_t)bm * K;
    const int8_t* pB1 = B1g + (size_t)bn * K;
    const int8_t* pB2 = B2g + (size_t)bn * K;

    const int NSg = K >> 7;

    auto load_stage = [&](int s) {
        const uint32_t stg = sb + (s & 1) * QS_STG;
        const int kk = s << 7;
        #pragma unroll
        for (int j = 0; j < 4; j++) {           // A: 128 rows x 8 chunks
            int id = tid + 256 * j;
            int r = id >> 3, c = (id & 7) * 16;
            uint32_t off = swz((uint32_t)(r * 128 + c));
            const size_t gsrc = (size_t)r * K + kk + c;
            CP16(stg + QS_A1 + off, pA1 + gsrc);
            CP16(stg + QS_A2 + off, pA2 + gsrc);
        }
        #pragma unroll
        for (int j = 0; j < 1; j++) {           // B: 64 rows x 8 chunks = 512 chunks
            int id = tid + 256 * j;
            int r = id >> 3, c = (id & 7) * 16;
            uint32_t off = swz((uint32_t)(r * 128 + c));
            const size_t gsrc = (size_t)r * K + kk + c;
            CP16(stg + QS_B1 + off, pB1 + gsrc);
            CP16(stg + QS_B2 + off, pB2 + gsrc);
            // second half of B chunks
            int id2 = tid + 256;
            int r2 = id2 >> 3, c2 = (id2 & 7) * 16;
            uint32_t off2 = swz((uint32_t)(r2 * 128 + c2));
            const size_t gsrc2 = (size_t)r2 * K + kk + c2;
            CP16(stg + QS_B1 + off2, pB1 + gsrc2);
            CP16(stg + QS_B2 + off2, pB2 + gsrc2);
        }
        CPCOMMIT();
    };

    load_stage(0);

    for (int s = 0; s < NSg; s++) {
        if (s + 1 < NSg) { load_stage(s + 1); CPWAIT(1); }
        else             { CPWAIT(0); }
        __syncthreads();
        const uint32_t stg = sb + (s & 1) * QS_STG;

        #pragma unroll
        for (int kk = 0; kk < 4; kk++) {
            // B fragments (both limbs): one ldsm.x4 covers 2 n-tiles
            uint32_t B1f[2][2], B2f[2][2];
            {
                int br = wn * 16 + ((lane >> 4) << 3) + (lane & 7);
                uint32_t boff = swz((uint32_t)(br * 128 + kk * 32 + ((lane >> 3) & 1) * 16));
                uint32_t t[4];
                ldm4s(t, stg + QS_B1 + boff);
                B1f[0][0] = t[0]; B1f[0][1] = t[1]; B1f[1][0] = t[2]; B1f[1][1] = t[3];
                ldm4s(t, stg + QS_B2 + boff);
                B2f[0][0] = t[0]; B2f[0][1] = t[1]; B2f[1][0] = t[2]; B2f[1][1] = t[3];
            }
            uint32_t Af[4][4];
            const int ar = wm * 64 + (lane & 15);
            const uint32_t acol = kk * 32 + (lane >> 4) * 16;
            #pragma unroll
            for (int mt = 0; mt < 4; mt++)
                ldm4s(Af[mt], stg + QS_A1 + swz((uint32_t)((ar + mt * 16) * 128) + acol));
            #pragma unroll
            for (int mt = 0; mt < 4; mt++)
                #pragma unroll
                for (int nt = 0; nt < 2; nt++) {
                    imma(P0[mt][nt], Af[mt], B1f[nt]);
                    imma(P1[mt][nt], Af[mt], B2f[nt]);
                }
            #pragma unroll
            for (int mt = 0; mt < 4; mt++)
                ldm4s(Af[mt], stg + QS_A2 + swz((uint32_t)((ar + mt * 16) * 128) + acol));
            #pragma unroll
            for (int mt = 0; mt < 4; mt++)
                #pragma unroll
                for (int nt = 0; nt < 2; nt++) {
                    imma(P1[mt][nt], Af[mt], B1f[nt]);
                    imma(P2[mt][nt], Af[mt], B2f[nt]);
                }
        }
        __syncthreads();
    }

    // ---- epilogue ----
    const float c1s = 1.f / 254.f;
    const float c2s = 1.f / (254.f * 254.f);
    #pragma unroll
    for (int mt = 0; mt < 4; mt++) {
        #pragma unroll
        for (int nt = 0; nt < 2; nt++) {
            const int rr = bm + wm * 64 + mt * 16 + (lane >> 2);
            const int cc = bn + wn * 16 + nt * 8 + (lane & 3) * 2;
            const float sb0 = sB[cc];
            const float sb1 = sB[cc + 1];
            float bi0 = 0.f, bi1 = 0.f;
            if (MODE != 3) { bi0 = bias[cc]; bi1 = bias[cc + 1]; }
            #pragma unroll
            for (int h = 0; h < 2; h++) {
                const int r = rr + h * 8;
                const float sa = sA[r];
                float v0 = fmaf((float)P2[mt][nt][h*2],   c2s,
                           fmaf((float)P1[mt][nt][h*2],   c1s, (float)P0[mt][nt][h*2]));
                float v1 = fmaf((float)P2[mt][nt][h*2+1], c2s,
                           fmaf((float)P1[mt][nt][h*2+1], c1s, (float)P0[mt][nt][h*2+1]));
                v0 = v0 * (sa * sb0) + bi0;
                v1 = v1 * (sa * sb1) + bi1;
                if (MODE == 1) {
                    v0 = 0.5f * v0 * (1.f + erff(v0 * 0.70710678118654752f));
                    v1 = 0.5f * v1 * (1.f + erff(v1 * 0.70710678118654752f));
                }
                if (MODE == 2) {
                    v0 += res[(size_t)r * N + cc];
                    v1 += res[(size_t)r * N + cc + 1];
                }
                float2 o; o.x = v0; o.y = v1;
                *(float2*)(C + (size_t)r * N + cc) = o;
            }
        }
    }
}

// ---------------- causal flash attention (fp32) ------------------------
__global__ void __launch_bounds__(256) attn_kernel(const float* __restrict__ q,
                                                   const float* __restrict__ k,
                                                   const float* __restrict__ v,
                                                   float* __restrict__ y)
{
    __shared__ __align__(16) float Qs[64][68];
    __shared__ __align__(16) float Ks[32][68];
    __shared__ __align__(16) float Vs[32][68];
    __shared__ __align__(16) float Ss[64][36];

    int bh = blockIdx.x;
    int b  = bh / HGPT;
    int h  = bh % HGPT;
    int qb = blockIdx.y;
    int tid = threadIdx.x;

    const float* qbase = q + ((size_t)(b * TGPT + qb * 64)) * DGPT + h * HDH;
    const float* kbase = k + ((size_t)(b * TGPT)) * DGPT + h * HDH;
    const float* vbase = v + ((size_t)(b * TGPT)) * DGPT + h * HDH;

    for (int f = tid; f < 1024; f += 256) {
        int r = f >> 4, c4 = (f & 15) * 4;
        *(float4*)&Qs[r][c4] = *(const float4*)(qbase + (size_t)r * DGPT + c4);
    }

    int i  = tid >> 2;
    int cg = tid & 3;
    int d0 = cg * 16;
    int qglob = qb * 64 + i;

    float O[16];
    #pragma unroll
    for (int dd = 0; dd < 16; dd++) O[dd] = 0.f;
    float m_run = -1e30f, l_run = 0.f;

    int nchunks = 2 * qb + 2;
    __syncthreads();

    for (int ch = 0; ch < nchunks; ch++) {
        int j0 = ch * 32;
        for (int f = tid; f < 512; f += 256) {
            int r = f >> 4, c4 = (f & 15) * 4;
            *(float4*)&Ks[r][c4] = *(const float4*)(kbase + (size_t)(j0 + r) * DGPT + c4);
            *(float4*)&Vs[r][c4] = *(const float4*)(vbase + (size_t)(j0 + r) * DGPT + c4);
        }
        __syncthreads();

        float sv[8];
        #pragma unroll
        for (int cc = 0; cc < 8; cc++) sv[cc] = 0.f;
        #pragma unroll 8
        for (int d = 0; d < 64; d++) {
            float qd = Qs[i][d];
            #pragma unroll
            for (int cc = 0; cc < 8; cc++)
                sv[cc] = fmaf(qd, Ks[cg * 8 + cc][d], sv[cc]);
        }
        float mloc = -1e30f;
        #pragma unroll
        for (int cc = 0; cc < 8; cc++) {
            float s = sv[cc] * 0.125f;
            if (j0 + cg * 8 + cc > qglob) s = -1e30f;
            sv[cc] = s;
            mloc = fmaxf(mloc, s);
        }
        mloc = fmaxf(mloc, __shfl_xor_sync(0xffffffffu, mloc, 1));
        mloc = fmaxf(mloc, __shfl_xor_sync(0xffffffffu, mloc, 2));

        float mnew = fmaxf(m_run, mloc);
        float corr = expf(m_run - mnew);
        float psum = 0.f;
        #pragma unroll
        for (int cc = 0; cc < 8; cc++) {
            float p = expf(sv[cc] - mnew);
            Ss[i][cg * 8 + cc] = p;
            psum += p;
        }
        psum += __shfl_xor_sync(0xffffffffu, psum, 1);
        psum += __shfl_xor_sync(0xffffffffu, psum, 2);
        l_run = l_run * corr + psum;
        m_run = mnew;
        #pragma unroll
        for (int dd = 0; dd < 16; dd++) O[dd] *= corr;
        __syncwarp();

        #pragma unroll 4
        for (int c = 0; c < 32; c++) {
            float p = Ss[i][c];
            float4 v0 = *(const float4*)&Vs[c][d0];
            float4 v1 = *(const float4*)&Vs[c][d0 + 4];
            float4 v2 = *(const float4*)&Vs[c][d0 + 8];
            float4 v3 = *(const float4*)&Vs[c][d0 + 12];
            O[0]  = fmaf(p, v0.x, O[0]);  O[1]  = fmaf(p, v0.y, O[1]);
            O[2]  = fmaf(p, v0.z, O[2]);  O[3]  = fmaf(p, v0.w, O[3]);
            O[4]  = fmaf(p, v1.x, O[4]);  O[5]  = fmaf(p, v1.y, O[5]);
            O[6]  = fmaf(p, v1.z, O[6]);  O[7]  = fmaf(p, v1.w, O[7]);
            O[8]  = fmaf(p, v2.x, O[8]);  O[9]  = fmaf(p, v2.y, O[9]);
            O[10] = fmaf(p, v2.z, O[10]); O[11] = fmaf(p, v2.w, O[11]);
            O[12] = fmaf(p, v3.x, O[12]); O[13] = fmaf(p, v3.y, O[13]);
            O[14] = fmaf(p, v3.z, O[14]); O[15] = fmaf(p, v3.w, O[15]);
        }
        __syncthreads();
    }

    float inv = 1.f / l_run;
    float* yp = y + ((size_t)(b * TGPT + qglob)) * DGPT + h * HDH + d0;
    #pragma unroll
    for (int dd = 0; dd < 16; dd++) yp[dd] = O[dd] * inv;
}

// ---------------- launcher ----------------
extern "C" void kernel_launch(void* const* d_in, const int* in_sizes, int n_in,
                              void* d_out, int out_size)
{
    const int*   idx    = (const int*)  d_in[0];
    const float* tok    = (const float*)d_in[1];
    const float* pos    = (const float*)d_in[2];
    const float* ln1_w  = (const float*)d_in[3];
    const float* ln1_b  = (const float*)d_in[4];
    const float* Wq     = (const float*)d_in[5];
    const float* bq     = (const float*)d_in[6];
    const float* Wk     = (const float*)d_in[7];
    const float* bk     = (const float*)d_in[8];
    const float* Wv     = (const float*)d_in[9];
    const float* bv     = (const float*)d_in[10];
    const float* Wproj  = (const float*)d_in[11];
    const float* bproj  = (const float*)d_in[12];
    const float* ln2_w  = (const float*)d_in[13];
    const float* ln2_b  = (const float*)d_in[14];
    const float* W1     = (const float*)d_in[15];
    const float* b1     = (const float*)d_in[16];
    const float* W2     = (const float*)d_in[17];
    const float* b2     = (const float*)d_in[18];
    const float* lnf_w  = (const float*)d_in[19];
    const float* lnf_b  = (const float*)d_in[20];
    const float* Wlogit = (const float*)d_in[21];
    const float* Wdev   = (const float*)d_in[22];
    float* out = (float*)d_out;

    float *xp, *qp, *kp, *vp, *hp, *fp, *swp, *sap;
    int8_t *wa, *wb, *qa, *qb;
    cudaGetSymbolAddress((void**)&xp, g_x);
    cudaGetSymbolAddress((void**)&qp, g_q);
    cudaGetSymbolAddress((void**)&kp, g_k);
    cudaGetSymbolAddress((void**)&vp, g_v);
    cudaGetSymbolAddress((void**)&hp, g_h);
    cudaGetSymbolAddress((void**)&fp, g_ff);
    cudaGetSymbolAddress((void**)&wa, g_wa);
    cudaGetSymbolAddress((void**)&wb, g_wb);
    cudaGetSymbolAddress((void**)&qa, g_qa);
    cudaGetSymbolAddress((void**)&qb, g_qb);
    cudaGetSymbolAddress((void**)&swp, g_sw);
    cudaGetSymbolAddress((void**)&sap, g_sa);

    cudaFuncSetAttribute(gemm8<0>, cudaFuncAttributeMaxDynamicSharedMemorySize, Q_SMEM);
    cudaFuncSetAttribute(gemm8<1>, cudaFuncAttributeMaxDynamicSharedMemorySize, Q_SMEM);
    cudaFuncSetAttribute(gemm8<2>, cudaFuncAttributeMaxDynamicSharedMemorySize, Q_SMEM);
    cudaFuncSetAttribute(gemm8<3>, cudaFuncAttributeMaxDynamicSharedMemorySize, Q_SMEM);

    // quantize all weights once (per output-row scaling over K)
    quant_kernel<<<8192, 256>>>(Wq,     wa + O_WQ,  wb + O_WQ,  swp + RO_WQ,  1024);
    quant_kernel<<<8192, 256>>>(Wk,     wa + O_WK,  wb + O_WK,  swp + RO_WK,  1024);
    quant_kernel<<<8192, 256>>>(Wv,     wa + O_WV,  wb + O_WV,  swp + RO_WV,  1024);
    quant_kernel<<<8192, 256>>>(Wproj,  wa + O_WP,  wb + O_WP,  swp + RO_WP,  1024);
    quant_kernel<<<32768, 256>>>(W1,    wa + O_W1,  wb + O_W1,  swp + RO_W1,  1024);
    quant_kernel<<<8192, 256>>>(W2,     wa + O_W2,  wb + O_W2,  swp + RO_W2,  4096);
    quant_kernel<<<4096, 256>>>(Wlogit, wa + O_WLG, wb + O_WLG, swp + RO_WLG, 1024);
    quant_kernel<<<4096, 256>>>(Wdev,   wa + O_WDV, wb + O_WDV, swp + RO_WDV, 1024);

    dim3 gD(DGPT / 64, MGPT / 128);    // (16, 32)
    dim3 gF(FGPT / 64, MGPT / 128);    // (64, 32)
    dim3 gV(VGPT / 64, MGPT / 128);    // (64, 32)
    dim3 gA(BGPT * HGPT, TGPT / 64);

    embed_kernel<<<(MGPT * DGPT + 255) / 256, 256>>>(idx, tok, pos, xp);

    for (int l = 0; l < LGPT; l++) {
        size_t oD  = (size_t)l * DGPT * DGPT;
        size_t oF  = (size_t)l * FGPT * DGPT;
        size_t ob  = (size_t)l * DGPT;
        size_t obf = (size_t)l * FGPT;

        lnq_kernel<<<MGPT, 256>>>(xp, qa, qb, sap, ln1_w + ob, ln1_b + ob);
        gemm8<0><<<gD, 256, Q_SMEM>>>(qa, qb, sap, wa + O_WQ + oD, wb + O_WQ + oD,
                                      swp + RO_WQ + l * DGPT, bq + ob, nullptr, qp,
                                      MGPT, DGPT, DGPT);
        gemm8<0><<<gD, 256, Q_SMEM>>>(qa, qb, sap, wa + O_WK + oD, wb + O_WK + oD,
                                      swp + RO_WK + l * DGPT, bk + ob, nullptr, kp,
                                      MGPT, DGPT, DGPT);
        gemm8<0><<<gD, 256, Q_SMEM>>>(qa, qb, sap, wa + O_WV + oD, wb + O_WV + oD,
                                      swp + RO_WV + l * DGPT, bv + ob, nullptr, vp,
                                      MGPT, DGPT, DGPT);
        attn_kernel<<<gA, 256>>>(qp, kp, vp, hp);
        quant_kernel<<<MGPT, 256>>>(hp, qa, qb, sap, DGPT);
        gemm8<2><<<gD, 256, Q_SMEM>>>(qa, qb, sap, wa + O_WP + oD, wb + O_WP + oD,
                                      swp + RO_WP + l * DGPT, bproj + ob, xp, xp,
                                      MGPT, DGPT, DGPT);

        lnq_kernel<<<MGPT, 256>>>(xp, qa, qb, sap, ln2_w + ob, ln2_b + ob);
        gemm8<1><<<gF, 256, Q_SMEM>>>(qa, qb, sap, wa + O_W1 + oF, wb + O_W1 + oF,
                                      swp + RO_W1 + l * FGPT, b1 + obf, nullptr, fp,
                                      MGPT, FGPT, DGPT);
        quant_kernel<<<MGPT, 256>>>(fp, qa, qb, sap, FGPT);
        gemm8<2><<<gD, 256, Q_SMEM>>>(qa, qb, sap, wa + O_W2 + oF, wb + O_W2 + oF,
                                      swp + RO_W2 + l * DGPT, b2 + ob, xp, xp,
                                      MGPT, DGPT, FGPT);
    }

    lnq_kernel<<<MGPT, 256>>>(xp, qa, qb, sap, lnf_w, lnf_b);
    gemm8<3><<<gV, 256, Q_SMEM>>>(qa, qb, sap, wa + O_WLG, wb + O_WLG,
                                  swp + RO_WLG, nullptr, nullptr, out,
                                  MGPT, VGPT, DGPT);
    gemm8<3><<<gV, 256, Q_SMEM>>>(qa, qb, sap, wa + O_WDV, wb + O_WDV,
                                  swp + RO_WDV, nullptr, nullptr, out + (size_t)MGPT * VGPT,
                                  MGPT, VGPT, DGPT);
}

// round 6
// speedup vs baseline: 1.7947x; 1.7947x over previous
#include <cuda_runtime.h>
#include <cuda_bf16.h>
#include <math.h>
#include <stdint.h>

// ---------------- problem constants ----------------
#define BGPT 4
#define TGPT 1024
#define DGPT 1024
#define HGPT 16
#define HDH  64
#define LGPT 8
#define VGPT 4096
#define MGPT (BGPT*TGPT)   // 4096 tokens
#define FGPT (4*DGPT)      // 4096 ff dim

// weight scratch offsets (elements)
#define SZ_WQ   ((size_t)LGPT*DGPT*DGPT)
#define SZ_W1   ((size_t)LGPT*FGPT*DGPT)
#define SZ_HEAD ((size_t)VGPT*DGPT)
#define O_WQ    ((size_t)0)
#define O_WK    (O_WQ + SZ_WQ)
#define O_WV    (O_WK + SZ_WQ)
#define O_WP    (O_WV + SZ_WQ)
#define O_W1    (O_WP + SZ_WQ)
#define O_W2    (O_W1 + SZ_W1)
#define O_WLG   (O_W2 + SZ_W1)
#define O_WDV   (O_WLG + SZ_HEAD)
#define WTOT    (O_WDV + SZ_HEAD)

// ---------------- scratch (device globals; no allocs allowed) ----------------
__device__ float g_x [MGPT*DGPT];                    // residual stream (fp32)
__device__ float g_q [MGPT*DGPT];
__device__ float g_k [MGPT*DGPT];
__device__ float g_v [MGPT*DGPT];
__device__ __nv_bfloat16 g_ahi[(size_t)MGPT*DGPT];   // activation hi (LN out / attn out)
__device__ __nv_bfloat16 g_alo[(size_t)MGPT*DGPT];
__device__ __nv_bfloat16 g_fhi[(size_t)MGPT*FGPT];   // ff activation hi
__device__ __nv_bfloat16 g_flo[(size_t)MGPT*FGPT];
__device__ __nv_bfloat16 g_whi[WTOT];                // split weights
__device__ __nv_bfloat16 g_wlo[WTOT];

// ---------------- helpers ----------------
__device__ __forceinline__ void split_bf16(float v, __nv_bfloat16& h, __nv_bfloat16& l)
{
    h = __float2bfloat16_rn(v);
    l = __float2bfloat16_rn(v - __bfloat162float(h));
}
__device__ __forceinline__ uint32_t smem_u32(const void* p) {
    uint32_t a;
    asm("{ .reg .u64 t; cvta.to.shared.u64 t, %1; cvt.u32.u64 %0, t; }" : "=r"(a) : "l"(p));
    return a;
}
#define CP16(dst, src) \
    asm volatile("cp.async.cg.shared.global [%0], [%1], 16;\n" :: "r"(dst), "l"(src))
#define CPCOMMIT() asm volatile("cp.async.commit_group;\n" ::: "memory")
#define CPWAIT(n)  asm volatile("cp.async.wait_group %0;\n" :: "n"(n) : "memory")

// ---------------- embedding ----------------
__global__ void embed_kernel(const int* __restrict__ idx,
                             const float* __restrict__ tok,
                             const float* __restrict__ pos,
                             float* __restrict__ x)
{
    int i = blockIdx.x * blockDim.x + threadIdx.x;
    if (i >= MGPT * DGPT) return;
    int row = i / DGPT;
    int d   = i - row * DGPT;
    int t   = row & (TGPT - 1);
    x[i] = tok[(size_t)idx[row] * DGPT + d] + pos[(size_t)t * DGPT + d];
}

// ---------------- fp32 -> bf16 hi/lo split (weights only) ----------------
__global__ void __launch_bounds__(256) convsplit_kernel(const float* __restrict__ in,
                                                        __nv_bfloat16* __restrict__ hi,
                                                        __nv_bfloat16* __restrict__ lo,
                                                        size_t n4)
{
    size_t i = (size_t)blockIdx.x * blockDim.x + threadIdx.x;
    if (i >= n4) return;
    size_t e = i * 4;
    float4 v = *(const float4*)(in + e);
    __nv_bfloat16 hx, hy, hz, hw, lx, ly, lz, lw;
    split_bf16(v.x, hx, lx); split_bf16(v.y, hy, ly);
    split_bf16(v.z, hz, lz); split_bf16(v.w, hw, lw);
    __nv_bfloat162 h01 = __halves2bfloat162(hx, hy);
    __nv_bfloat162 h23 = __halves2bfloat162(hz, hw);
    __nv_bfloat162 l01 = __halves2bfloat162(lx, ly);
    __nv_bfloat162 l23 = __halves2bfloat162(lz, lw);
    uint2 ho, loo;
    ho.x  = *(uint32_t*)&h01; ho.y  = *(uint32_t*)&h23;
    loo.x = *(uint32_t*)&l01; loo.y = *(uint32_t*)&l23;
    *(uint2*)(hi + e) = ho;
    *(uint2*)(lo + e) = loo;
}

// ---------------- layernorm: fp32 in -> bf16 hi/lo out ----------------
__global__ void __launch_bounds__(256) ln_kernel(const float* __restrict__ in,
                                                 __nv_bfloat16* __restrict__ ohi,
                                                 __nv_bfloat16* __restrict__ olo,
                                                 const float* __restrict__ w,
                                                 const float* __restrict__ b)
{
    int row = blockIdx.x;
    const float* x = in + (size_t)row * DGPT;
    int tid = threadIdx.x;
    __shared__ float red[8];

    float s = 0.f;
    for (int d = tid; d < DGPT; d += 256) s += x[d];
    #pragma unroll
    for (int o = 16; o; o >>= 1) s += __shfl_xor_sync(0xffffffffu, s, o);
    if ((tid & 31) == 0) red[tid >> 5] = s;
    __syncthreads();
    if (tid < 32) {
        float v = (tid < 8) ? red[tid] : 0.f;
        #pragma unroll
        for (int o = 4; o; o >>= 1) v += __shfl_xor_sync(0xffffffffu, v, o);
        if (tid == 0) red[0] = v;
    }
    __syncthreads();
    float mean = red[0] * (1.f / DGPT);

    float q = 0.f;
    for (int d = tid; d < DGPT; d += 256) { float t = x[d] - mean; q += t * t; }
    __syncthreads();
    #pragma unroll
    for (int o = 16; o; o >>= 1) q += __shfl_xor_sync(0xffffffffu, q, o);
    if ((tid & 31) == 0) red[tid >> 5] = q;
    __syncthreads();
    if (tid < 32) {
        float v = (tid < 8) ? red[tid] : 0.f;
        #pragma unroll
        for (int o = 4; o; o >>= 1) v += __shfl_xor_sync(0xffffffffu, v, o);
        if (tid == 0) red[0] = v;
    }
    __syncthreads();
    float rstd = rsqrtf(red[0] * (1.f / DGPT) + 1e-5f);

    for (int d = tid; d < DGPT; d += 256) {
        float v = (x[d] - mean) * rstd * w[d] + b[d];
        __nv_bfloat16 h, l;
        split_bf16(v, h, l);
        ohi[(size_t)row * DGPT + d] = h;
        olo[(size_t)row * DGPT + d] = l;
    }
}

// ---------------- tensor-core GEMM helpers ----------------
__device__ __forceinline__ void ldm4(uint32_t r[4], const __nv_bfloat16* p)
{
    uint32_t a = (uint32_t)__cvta_generic_to_shared(p);
    asm volatile("ldmatrix.sync.aligned.m8n8.x4.shared.b16 {%0,%1,%2,%3}, [%4];\n"
                 : "=r"(r[0]), "=r"(r[1]), "=r"(r[2]), "=r"(r[3]) : "r"(a));
}

__device__ __forceinline__ void mma16816(float c[4], const uint32_t a[4], const uint32_t b[2])
{
    asm volatile(
        "mma.sync.aligned.m16n8k16.row.col.f32.bf16.bf16.f32 "
        "{%0,%1,%2,%3}, {%4,%5,%6,%7}, {%8,%9}, {%0,%1,%2,%3};\n"
        : "+f"(c[0]), "+f"(c[1]), "+f"(c[2]), "+f"(c[3])
        : "r"(a[0]), "r"(a[1]), "r"(a[2]), "r"(a[3]), "r"(b[0]), "r"(b[1]));
}

// ---------------- GEMM: C[M,N] = A[M,K] @ W[N,K]^T  (bf16x3, fp32 acc) ----
// CTA 128x128, BK=32, 8 warps (warp 64x32), 4-stage cp.async pipeline.
// MODE: 0 = +bias (fp32 out) | 1 = +bias, GELU, bf16 hi/lo out
//       2 = +bias +res (fp32 out) | 3 = plain fp32 out
#define BKg 32
#define PK  40
#define SMBUF   (128*PK)            // elems per matrix per stage (5120)
#define SMBUFB  (SMBUF*2)           // bytes per matrix per stage (10240)
#define STAGEE  (4*SMBUF)           // elems per stage (20480)
#define STAGEB  (4*SMBUFB)          // bytes per stage (40960)
#define NSTG    4
#define GSMEM_BYTES (NSTG*STAGEB)   // 163840 bytes

template<int MODE>
__global__ void __launch_bounds__(256) gemm_tc(
    const __nv_bfloat16* __restrict__ Ahi, const __nv_bfloat16* __restrict__ Alo,
    const __nv_bfloat16* __restrict__ Whi, const __nv_bfloat16* __restrict__ Wlo,
    const float* __restrict__ bias, const float* __restrict__ res,
    float* __restrict__ C,
    __nv_bfloat16* __restrict__ Chi, __nv_bfloat16* __restrict__ Clo,
    int M, int N, int K)
{
    extern __shared__ __align__(128) __nv_bfloat16 sm[];
    const uint32_t sb = smem_u32(sm);

    const int tid  = threadIdx.x;
    const int lane = tid & 31;
    const int wid  = tid >> 5;
    const int wm   = wid >> 2;          // 0..1
    const int wn   = wid & 3;           // 0..3
    const int bm   = blockIdx.y * 128;
    const int bn   = blockIdx.x * 128;

    // ldmatrix geometry (identical to proven R4 layout)
    const int a_r = wm * 64 + (lane & 15);
    const int a_c = (lane >> 4) * 8;
    const int b_r = wn * 32 + (lane >> 4) * 8 + (lane & 7);
    const int b_c = ((lane >> 3) & 1) * 8;

    float acc[4][4][4];
    #pragma unroll
    for (int mi = 0; mi < 4; mi++)
        #pragma unroll
        for (int ni = 0; ni < 4; ni++)
            #pragma unroll
            for (int r = 0; r < 4; r++) acc[mi][ni][r] = 0.f;

    // cp.async load geometry: 512 16B-chunks per matrix per stage, 2 per thread
    const __nv_bfloat16* pAh = Ahi + (size_t)bm * K;
    const __nv_bfloat16* pAl = Alo + (size_t)bm * K;
    const __nv_bfloat16* pBh = Whi + (size_t)bn * K;
    const __nv_bfloat16* pBl = Wlo + (size_t)bn * K;

    const int NS = K / BKg;

    auto load_stage = [&](int s) {
        const uint32_t stb = sb + (uint32_t)(s & (NSTG - 1)) * STAGEB;
        const int kk = s * BKg;
        #pragma unroll
        for (int j = 0; j < 2; j++) {
            const int c   = tid + j * 256;     // 0..511
            const int row = c >> 2;
            const int ce  = (c & 3) * 8;       // elem col within BK
            const uint32_t doff = (uint32_t)(row * (PK * 2) + (c & 3) * 16);
            const size_t g = (size_t)row * K + kk + ce;
            CP16(stb + 0 * SMBUFB + doff, pAh + g);
            CP16(stb + 1 * SMBUFB + doff, pAl + g);
            CP16(stb + 2 * SMBUFB + doff, pBh + g);
            CP16(stb + 3 * SMBUFB + doff, pBl + g);
        }
        CPCOMMIT();
    };

    load_stage(0);
    load_stage(1);
    load_stage(2);

    for (int s = 0; s < NS; s++) {
        if (s + 2 < NS)      CPWAIT(2);
        else if (s + 1 < NS) CPWAIT(1);
        else                 CPWAIT(0);
        __syncthreads();
        if (s + 3 < NS) load_stage(s + 3);

        const __nv_bfloat16* stg = sm + (s & (NSTG - 1)) * STAGEE;
        const __nv_bfloat16* sAh = stg;
        const __nv_bfloat16* sAl = stg + SMBUF;
        const __nv_bfloat16* sBh = stg + 2 * SMBUF;
        const __nv_bfloat16* sBl = stg + 3 * SMBUF;

        #pragma unroll
        for (int ks = 0; ks < 2; ks++) {
            const int k0 = ks * 16;
            uint32_t afh[4][4], afl[4][4];
            #pragma unroll
            for (int mi = 0; mi < 4; mi++) {
                const int off = (a_r + mi * 16) * PK + k0 + a_c;
                ldm4(afh[mi], sAh + off);
                ldm4(afl[mi], sAl + off);
            }
            uint32_t bfh[4][2], bfl[4][2];
            #pragma unroll
            for (int np = 0; np < 2; np++) {
                const int off = (b_r + np * 16) * PK + k0 + b_c;
                uint32_t t[4];
                ldm4(t, sBh + off);
                bfh[np * 2][0] = t[0]; bfh[np * 2][1] = t[1];
                bfh[np * 2 + 1][0] = t[2]; bfh[np * 2 + 1][1] = t[3];
                ldm4(t, sBl + off);
                bfl[np * 2][0] = t[0]; bfl[np * 2][1] = t[1];
                bfl[np * 2 + 1][0] = t[2]; bfl[np * 2 + 1][1] = t[3];
            }
            // term-outermost ordering: accumulator reuse distance = 16 MMAs
            #pragma unroll
            for (int mi = 0; mi < 4; mi++)
                #pragma unroll
                for (int ni = 0; ni < 4; ni++)
                    mma16816(acc[mi][ni], afh[mi], bfh[ni]);
            #pragma unroll
            for (int mi = 0; mi < 4; mi++)
                #pragma unroll
                for (int ni = 0; ni < 4; ni++)
                    mma16816(acc[mi][ni], afh[mi], bfl[ni]);
            #pragma unroll
            for (int mi = 0; mi < 4; mi++)
                #pragma unroll
                for (int ni = 0; ni < 4; ni++)
                    mma16816(acc[mi][ni], afl[mi], bfh[ni]);
        }
    }

    // epilogue
    const int er = bm + wm * 64 + (lane >> 2);
    const int ec = bn + wn * 32 + (lane & 3) * 2;
    #pragma unroll
    for (int mi = 0; mi < 4; mi++) {
        #pragma unroll
        for (int ni = 0; ni < 4; ni++) {
            const int col = ec + ni * 8;
            #pragma unroll
            for (int h = 0; h < 2; h++) {
                const size_t row = (size_t)(er + mi * 16 + h * 8);
                float v0 = acc[mi][ni][h * 2];
                float v1 = acc[mi][ni][h * 2 + 1];
                if (MODE != 3) { v0 += bias[col]; v1 += bias[col + 1]; }
                if (MODE == 1) {
                    v0 = 0.5f * v0 * (1.f + erff(v0 * 0.70710678118654752f));
                    v1 = 0.5f * v1 * (1.f + erff(v1 * 0.70710678118654752f));
                    __nv_bfloat16 h0, l0, h1, l1;
                    split_bf16(v0, h0, l0);
                    split_bf16(v1, h1, l1);
                    *(__nv_bfloat162*)(Chi + row * N + col) = __halves2bfloat162(h0, h1);
                    *(__nv_bfloat162*)(Clo + row * N + col) = __halves2bfloat162(l0, l1);
                } else {
                    if (MODE == 2) {
                        v0 += res[row * N + col];
                        v1 += res[row * N + col + 1];
                    }
                    float2 o; o.x = v0; o.y = v1;
                    *(float2*)(C + row * N + col) = o;
                }
            }
        }
    }
}

// ---------------- causal flash attention (fp32, bf16 hi/lo out) ----------
__global__ void __launch_bounds__(256) attn_kernel(const float* __restrict__ q,
                                                   const float* __restrict__ k,
                                                   const float* __restrict__ v,
                                                   __nv_bfloat16* __restrict__ yhi,
                                                   __nv_bfloat16* __restrict__ ylo)
{
    __shared__ __align__(16) float Qs[64][68];
    __shared__ __align__(16) float Ks[32][68];
    __shared__ __align__(16) float Vs[32][68];
    __shared__ __align__(16) float Ss[64][36];

    int bh = blockIdx.x;
    int b  = bh / HGPT;
    int h  = bh % HGPT;
    int qb = blockIdx.y;
    int tid = threadIdx.x;

    const float* qbase = q + ((size_t)(b * TGPT + qb * 64)) * DGPT + h * HDH;
    const float* kbase = k + ((size_t)(b * TGPT)) * DGPT + h * HDH;
    const float* vbase = v + ((size_t)(b * TGPT)) * DGPT + h * HDH;

    for (int f = tid; f < 1024; f += 256) {
        int r = f >> 4, c4 = (f & 15) * 4;
        *(float4*)&Qs[r][c4] = *(const float4*)(qbase + (size_t)r * DGPT + c4);
    }

    int i  = tid >> 2;
    int cg = tid & 3;
    int d0 = cg * 16;
    int qglob = qb * 64 + i;

    float O[16];
    #pragma unroll
    for (int dd = 0; dd < 16; dd++) O[dd] = 0.f;
    float m_run = -1e30f, l_run = 0.f;

    int nchunks = 2 * qb + 2;
    __syncthreads();

    for (int ch = 0; ch < nchunks; ch++) {
        int j0 = ch * 32;
        for (int f = tid; f < 512; f += 256) {
            int r = f >> 4, c4 = (f & 15) * 4;
            *(float4*)&Ks[r][c4] = *(const float4*)(kbase + (size_t)(j0 + r) * DGPT + c4);
            *(float4*)&Vs[r][c4] = *(const float4*)(vbase + (size_t)(j0 + r) * DGPT + c4);
        }
        __syncthreads();

        float sv[8];
        #pragma unroll
        for (int cc = 0; cc < 8; cc++) sv[cc] = 0.f;
        #pragma unroll 8
        for (int d = 0; d < 64; d++) {
            float qd = Qs[i][d];
            #pragma unroll
            for (int cc = 0; cc < 8; cc++)
                sv[cc] = fmaf(qd, Ks[cg * 8 + cc][d], sv[cc]);
        }
        float mloc = -1e30f;
        #pragma unroll
        for (int cc = 0; cc < 8; cc++) {
            float s = sv[cc] * 0.125f;
            if (j0 + cg * 8 + cc > qglob) s = -1e30f;
            sv[cc] = s;
            mloc = fmaxf(mloc, s);
        }
        mloc = fmaxf(mloc, __shfl_xor_sync(0xffffffffu, mloc, 1));
        mloc = fmaxf(mloc, __shfl_xor_sync(0xffffffffu, mloc, 2));

        float mnew = fmaxf(m_run, mloc);
        float corr = expf(m_run - mnew);
        float psum = 0.f;
        #pragma unroll
        for (int cc = 0; cc < 8; cc++) {
            float p = expf(sv[cc] - mnew);
            Ss[i][cg * 8 + cc] = p;
            psum += p;
        }
        psum += __shfl_xor_sync(0xffffffffu, psum, 1);
        psum += __shfl_xor_sync(0xffffffffu, psum, 2);
        l_run = l_run * corr + psum;
        m_run = mnew;
        #pragma unroll
        for (int dd = 0; dd < 16; dd++) O[dd] *= corr;
        __syncwarp();

        #pragma unroll 4
        for (int c = 0; c < 32; c++) {
            float p = Ss[i][c];
            float4 v0 = *(const float4*)&Vs[c][d0];
            float4 v1 = *(const float4*)&Vs[c][d0 + 4];
            float4 v2 = *(const float4*)&Vs[c][d0 + 8];
            float4 v3 = *(const float4*)&Vs[c][d0 + 12];
            O[0]  = fmaf(p, v0.x, O[0]);  O[1]  = fmaf(p, v0.y, O[1]);
            O[2]  = fmaf(p, v0.z, O[2]);  O[3]  = fmaf(p, v0.w, O[3]);
            O[4]  = fmaf(p, v1.x, O[4]);  O[5]  = fmaf(p, v1.y, O[5]);
            O[6]  = fmaf(p, v1.z, O[6]);  O[7]  = fmaf(p, v1.w, O[7]);
            O[8]  = fmaf(p, v2.x, O[8]);  O[9]  = fmaf(p, v2.y, O[9]);
            O[10] = fmaf(p, v2.z, O[10]); O[11] = fmaf(p, v2.w, O[11]);
            O[12] = fmaf(p, v3.x, O[12]); O[13] = fmaf(p, v3.y, O[13]);
            O[14] = fmaf(p, v3.z, O[14]); O[15] = fmaf(p, v3.w, O[15]);
        }
        __syncthreads();
    }

    float inv = 1.f / l_run;
    size_t base = ((size_t)(b * TGPT + qglob)) * DGPT + h * HDH + d0;
    #pragma unroll
    for (int dd = 0; dd < 16; dd += 2) {
        float v0 = O[dd] * inv;
        float v1 = O[dd + 1] * inv;
        __nv_bfloat16 h0, l0, h1, l1;
        split_bf16(v0, h0, l0);
        split_bf16(v1, h1, l1);
        *(__nv_bfloat162*)(yhi + base + dd) = __halves2bfloat162(h0, h1);
        *(__nv_bfloat162*)(ylo + base + dd) = __halves2bfloat162(l0, l1);
    }
}

// ---------------- launcher ----------------
static inline void convsplit(const float* in, __nv_bfloat16* hi, __nv_bfloat16* lo, size_t n)
{
    size_t n4 = n / 4;
    convsplit_kernel<<<(unsigned)((n4 + 255) / 256), 256>>>(in, hi, lo, n4);
}

extern "C" void kernel_launch(void* const* d_in, const int* in_sizes, int n_in,
                              void* d_out, int out_size)
{
    const int*   idx    = (const int*)  d_in[0];
    const float* tok    = (const float*)d_in[1];
    const float* pos    = (const float*)d_in[2];
    const float* ln1_w  = (const float*)d_in[3];
    const float* ln1_b  = (const float*)d_in[4];
    const float* Wq     = (const float*)d_in[5];
    const float* bq     = (const float*)d_in[6];
    const float* Wk     = (const float*)d_in[7];
    const float* bk     = (const float*)d_in[8];
    const float* Wv     = (const float*)d_in[9];
    const float* bv     = (const float*)d_in[10];
    const float* Wproj  = (const float*)d_in[11];
    const float* bproj  = (const float*)d_in[12];
    const float* ln2_w  = (const float*)d_in[13];
    const float* ln2_b  = (const float*)d_in[14];
    const float* W1     = (const float*)d_in[15];
    const float* b1     = (const float*)d_in[16];
    const float* W2     = (const float*)d_in[17];
    const float* b2     = (const float*)d_in[18];
    const float* lnf_w  = (const float*)d_in[19];
    const float* lnf_b  = (const float*)d_in[20];
    const float* Wlogit = (const float*)d_in[21];
    const float* Wdev   = (const float*)d_in[22];
    float* out = (float*)d_out;

    float *xp, *qp, *kp, *vp;
    __nv_bfloat16 *whi, *wlo, *ahi, *alo, *fhi, *flo;
    cudaGetSymbolAddress((void**)&xp, g_x);
    cudaGetSymbolAddress((void**)&qp, g_q);
    cudaGetSymbolAddress((void**)&kp, g_k);
    cudaGetSymbolAddress((void**)&vp, g_v);
    cudaGetSymbolAddress((void**)&whi, g_whi);
    cudaGetSymbolAddress((void**)&wlo, g_wlo);
    cudaGetSymbolAddress((void**)&ahi, g_ahi);
    cudaGetSymbolAddress((void**)&alo, g_alo);
    cudaGetSymbolAddress((void**)&fhi, g_fhi);
    cudaGetSymbolAddress((void**)&flo, g_flo);

    cudaFuncSetAttribute(gemm_tc<0>, cudaFuncAttributeMaxDynamicSharedMemorySize, GSMEM_BYTES);
    cudaFuncSetAttribute(gemm_tc<1>, cudaFuncAttributeMaxDynamicSharedMemorySize, GSMEM_BYTES);
    cudaFuncSetAttribute(gemm_tc<2>, cudaFuncAttributeMaxDynamicSharedMemorySize, GSMEM_BYTES);
    cudaFuncSetAttribute(gemm_tc<3>, cudaFuncAttributeMaxDynamicSharedMemorySize, GSMEM_BYTES);

    // split all weights once
    convsplit(Wq,     whi + O_WQ,  wlo + O_WQ,  SZ_WQ);
    convsplit(Wk,     whi + O_WK,  wlo + O_WK,  SZ_WQ);
    convsplit(Wv,     whi + O_WV,  wlo + O_WV,  SZ_WQ);
    convsplit(Wproj,  whi + O_WP,  wlo + O_WP,  SZ_WQ);
    convsplit(W1,     whi + O_W1,  wlo + O_W1,  SZ_W1);
    convsplit(W2,     whi + O_W2,  wlo + O_W2,  SZ_W1);
    convsplit(Wlogit, whi + O_WLG, wlo + O_WLG, SZ_HEAD);
    convsplit(Wdev,   whi + O_WDV, wlo + O_WDV, SZ_HEAD);

    dim3 gD(DGPT / 128, MGPT / 128);
    dim3 gF(FGPT / 128, MGPT / 128);
    dim3 gV(VGPT / 128, MGPT / 128);
    dim3 gA(BGPT * HGPT, TGPT / 64);

    embed_kernel<<<(MGPT * DGPT + 255) / 256, 256>>>(idx, tok, pos, xp);

    for (int l = 0; l < LGPT; l++) {
        size_t oD  = (size_t)l * DGPT * DGPT;
        size_t oF  = (size_t)l * FGPT * DGPT;
        size_t ob  = (size_t)l * DGPT;
        size_t obf = (size_t)l * FGPT;

        ln_kernel<<<MGPT, 256>>>(xp, ahi, alo, ln1_w + ob, ln1_b + ob);
        gemm_tc<0><<<gD, 256, GSMEM_BYTES>>>(ahi, alo, whi + O_WQ + oD, wlo + O_WQ + oD,
                                             bq + ob, nullptr, qp, nullptr, nullptr,
                                             MGPT, DGPT, DGPT);
        gemm_tc<0><<<gD, 256, GSMEM_BYTES>>>(ahi, alo, whi + O_WK + oD, wlo + O_WK + oD,
                                             bk + ob, nullptr, kp, nullptr, nullptr,
                                             MGPT, DGPT, DGPT);
        gemm_tc<0><<<gD, 256, GSMEM_BYTES>>>(ahi, alo, whi + O_WV + oD, wlo + O_WV + oD,
                                             bv + ob, nullptr, vp, nullptr, nullptr,
                                             MGPT, DGPT, DGPT);
        attn_kernel<<<gA, 256>>>(qp, kp, vp, ahi, alo);
        gemm_tc<2><<<gD, 256, GSMEM_BYTES>>>(ahi, alo, whi + O_WP + oD, wlo + O_WP + oD,
                                             bproj + ob, xp, xp, nullptr, nullptr,
                                             MGPT, DGPT, DGPT);

        ln_kernel<<<MGPT, 256>>>(xp, ahi, alo, ln2_w + ob, ln2_b + ob);
        gemm_tc<1><<<gF, 256, GSMEM_BYTES>>>(ahi, alo, whi + O_W1 + oF, wlo + O_W1 + oF,
                                             b1 + obf, nullptr, nullptr, fhi, flo,
                                             MGPT, FGPT, DGPT);
        gemm_tc<2><<<gD, 256, GSMEM_BYTES>>>(fhi, flo, whi + O_W2 + oF, wlo + O_W2 + oF,
                                             b2 + ob, xp, xp, nullptr, nullptr,
                                             MGPT, DGPT, FGPT);
    }

    ln_kernel<<<MGPT, 256>>>(xp, ahi, alo, lnf_w, lnf_b);
    gemm_tc<3><<<gV, 256, GSMEM_BYTES>>>(ahi, alo, whi + O_WLG, wlo + O_WLG,
                                         nullptr, nullptr, out, nullptr, nullptr,
                                         MGPT, VGPT, DGPT);
    gemm_tc<3><<<gV, 256, GSMEM_BYTES>>>(ahi, alo, whi + O_WDV, wlo + O_WDV,
                                         nullptr, nullptr, out + (size_t)MGPT * VGPT, nullptr, nullptr,
                                         MGPT, VGPT, DGPT);
}